// round 6
// baseline (speedup 1.0000x reference)
#include <cuda_runtime.h>
#include <cstdint>
#include <math.h>

#define BATCH 8
#define CH 1024
#define SEQ 1024
#define HEADS 16
#define DHEAD 64
#define GROUPS 32
#define CPG (CH / GROUPS)
#define LAYERS 6
#define SPECD 80

// Scratch (device globals: allowed, no runtime allocation)
__device__ float g_x[BATCH * CH * SEQ];        // residual stream
__device__ float g_h[BATCH * CH * SEQ];        // groupnorm output
__device__ float g_qkv[BATCH * 3 * CH * SEQ];  // qkv activations
__device__ float g_ao[BATCH * CH * SEQ];       // attention output
__device__ float g_q0[BATCH * CH];             // last-layer q at t=0
__device__ float g_o0[BATCH * CH];             // last-layer attn out at t=0

// ---------------------------------------------------------------------------
// helpers
// ---------------------------------------------------------------------------
__device__ __forceinline__ float to_tf32(float x) {
    unsigned u;
    asm("cvt.rna.tf32.f32 %0, %1;" : "=r"(u) : "f"(x));
    return __uint_as_float(u);
}

// D(16x8) += A(16x8,row) * B(8x8,col) ; tf32 in, fp32 acc
__device__ __forceinline__ void mma_tf32(float* d, const float* a, const float* b) {
    asm volatile(
        "mma.sync.aligned.m16n8k8.row.col.f32.tf32.tf32.f32 "
        "{%0,%1,%2,%3}, {%4,%5,%6,%7}, {%8,%9}, {%0,%1,%2,%3};\n"
        : "+f"(d[0]), "+f"(d[1]), "+f"(d[2]), "+f"(d[3])
        : "r"(__float_as_uint(a[0])), "r"(__float_as_uint(a[1])),
          "r"(__float_as_uint(a[2])), "r"(__float_as_uint(a[3])),
          "r"(__float_as_uint(b[0])), "r"(__float_as_uint(b[1])));
}

// ---------------------------------------------------------------------------
// tf32 GEMM with fragment-major shared layout.
// out[b,gr(m),n] = bias[gr(m)] + (res? res) + sum_k W[gr(m),k] X[b,k,n]
// gr(m)=m (head_remap=0) or (m>>7)*192+64+(m&127) (head_remap=1).
// Block 128x128, kc=16, 8 warps (64x32 warp tile). M%128==0,N%128==0,K%16==0.
//
// As layout (per 16-k stage, 2048 floats): element (m,k) at
//   chunk*128 + lane*4 + slot, chunk=(m>>4)*2+(k>>3),
//   lane=(m&7)*4+(k&3), slot=((m>>3)&1)+((k>>2)&1)*2
// -> warp a-frag for tile (chunk) = one LDS.128 at lane*4.
// Bs layout: element (k,n) at
//   (k>>3)*1024 + (n>>3)*64 + ((( (n&7)*4+(k&3) ) + (n>>3)*4)&31)*2 + ((k>>2)&1)
// -> warp b-frag = one LDS.64 at ((lane + ntg*4)&31)*2.
// ---------------------------------------------------------------------------
__global__ __launch_bounds__(256) void gemm_tf32(
    const float* __restrict__ W, const float* __restrict__ X,
    const float* __restrict__ bias, const float* __restrict__ res,
    float* __restrict__ out, int M, int N, int K, size_t out_bstride,
    int head_remap)
{
    __shared__ __align__(16) float As[2][2048];
    __shared__ __align__(16) float Bs[2][2048];

    const int b  = blockIdx.z;
    const int m0 = blockIdx.y * 128;
    const int n0 = blockIdx.x * 128;
    const float* Xb = X + (size_t)b * K * N;

    const int tid  = threadIdx.x;
    const int lane = tid & 31;
    const int wid  = tid >> 5;
    const int wm   = wid & 1;
    const int wn   = wid >> 1;
    const int lg   = lane >> 2;
    const int lt   = lane & 3;

    // gmem load mapping
    const int a_row = tid >> 1;           // 0..127
    const int a_kb  = (tid & 1) * 8;      // 0 or 8
    const int b_row = tid >> 4;           // 0..15
    const int b_nb  = (tid & 15) * 8;     // 0..120

    const int a_grow = head_remap ? ((m0 >> 7) * 192 + 64 + a_row) : (m0 + a_row);

    // precomputed store bases
    const int a_sbase = ((a_row >> 4) * 2 + (a_kb >> 3)) * 128
                      + (a_row & 7) * 16 + ((a_row >> 3) & 1);
    const int a_rot   = a_row & 7;
    const int ntg_s   = b_nb >> 3;
    const int b_sbase = (b_row >> 3) * 1024 + ntg_s * 64 + ((b_row >> 2) & 1);
    const int b_k3    = b_row & 3;

    float acc[4][4][4];
#pragma unroll
    for (int i = 0; i < 4; i++)
#pragma unroll
        for (int j = 0; j < 4; j++)
#pragma unroll
            for (int r = 0; r < 4; r++) acc[i][j][r] = 0.f;

    // prologue: load + store k-stage 0
    {
        const float* wp = W + (size_t)a_grow * K + a_kb;
        float4 w0 = *(const float4*)(wp);
        float4 w1 = *(const float4*)(wp + 4);
        float w_arr[8] = {w0.x, w0.y, w0.z, w0.w, w1.x, w1.y, w1.z, w1.w};
        float* as = As[0];
#pragma unroll
        for (int j = 0; j < 8; j++) {
            const int i = (j + a_rot) & 7;
            as[a_sbase + (i & 3) * 4 + ((i >> 2) << 1)] = to_tf32(w_arr[i]);
        }
        const float* xp = Xb + (size_t)b_row * N + n0 + b_nb;
        float4 x0 = *(const float4*)(xp);
        float4 x1 = *(const float4*)(xp + 4);
        float x_arr[8] = {x0.x, x0.y, x0.z, x0.w, x1.x, x1.y, x1.z, x1.w};
        float* bs = Bs[0];
#pragma unroll
        for (int i = 0; i < 8; i++) {
            const int lp = ((i * 4 + b_k3) + ntg_s * 4) & 31;
            bs[b_sbase + lp * 2] = to_tf32(x_arr[i]);
        }
    }
    __syncthreads();

    int buf = 0;
    for (int k0 = 0; k0 < K; k0 += 16) {
        float4 w0, w1, x0, x1;
        const bool more = (k0 + 16) < K;
        if (more) {
            const float* wp = W + (size_t)a_grow * K + k0 + 16 + a_kb;
            w0 = *(const float4*)(wp);
            w1 = *(const float4*)(wp + 4);
            const float* xp = Xb + (size_t)(k0 + 16 + b_row) * N + n0 + b_nb;
            x0 = *(const float4*)(xp);
            x1 = *(const float4*)(xp + 4);
        }

        const float* as = As[buf];
        const float* bs = Bs[buf];
#pragma unroll
        for (int kkc = 0; kkc < 2; kkc++) {
            float4 a[4];
            float2 bb[4];
#pragma unroll
            for (int mt = 0; mt < 4; mt++)
                a[mt] = *(const float4*)&as[((wm * 4 + mt) * 2 + kkc) * 128 + lane * 4];
#pragma unroll
            for (int nt = 0; nt < 4; nt++) {
                const int ntg = wn * 4 + nt;
                bb[nt] = *(const float2*)&bs[kkc * 1024 + ntg * 64 +
                                             (((lane + ntg * 4) & 31) << 1)];
            }
#pragma unroll
            for (int mt = 0; mt < 4; mt++)
#pragma unroll
                for (int nt = 0; nt < 4; nt++)
                    mma_tf32(acc[mt][nt], (const float*)&a[mt], (const float*)&bb[nt]);
        }

        if (more) {
            float w_arr[8] = {w0.x, w0.y, w0.z, w0.w, w1.x, w1.y, w1.z, w1.w};
            float* asn = As[buf ^ 1];
#pragma unroll
            for (int j = 0; j < 8; j++) {
                const int i = (j + a_rot) & 7;
                asn[a_sbase + (i & 3) * 4 + ((i >> 2) << 1)] = to_tf32(w_arr[i]);
            }
            float x_arr[8] = {x0.x, x0.y, x0.z, x0.w, x1.x, x1.y, x1.z, x1.w};
            float* bsn = Bs[buf ^ 1];
#pragma unroll
            for (int i = 0; i < 8; i++) {
                const int lp = ((i * 4 + b_k3) + ntg_s * 4) & 31;
                bsn[b_sbase + lp * 2] = to_tf32(x_arr[i]);
            }
        }
        __syncthreads();
        buf ^= 1;
    }

    // epilogue (C-fragment layout unchanged)
    const size_t ob = (size_t)b * out_bstride;
#pragma unroll
    for (int mt = 0; mt < 4; mt++) {
        const int ml = m0 + wm * 64 + mt * 16 + lg;
        const int r0 = head_remap ? ((ml >> 7) * 192 + 64 + (ml & 127)) : ml;
        const float bi0 = bias[r0];
        const float bi1 = bias[r0 + 8];
#pragma unroll
        for (int nt = 0; nt < 4; nt++) {
            const int c = n0 + wn * 32 + nt * 8 + 2 * lt;
            float2 v0 = make_float2(acc[mt][nt][0] + bi0, acc[mt][nt][1] + bi0);
            float2 v1 = make_float2(acc[mt][nt][2] + bi1, acc[mt][nt][3] + bi1);
            const size_t o0 = ob + (size_t)r0 * N + c;
            const size_t o1 = ob + (size_t)(r0 + 8) * N + c;
            if (res) {
                float2 r0v = *(const float2*)(res + o0);
                float2 r1v = *(const float2*)(res + o1);
                v0.x += r0v.x; v0.y += r0v.y; v1.x += r1v.x; v1.y += r1v.y;
            }
            *(float2*)(out + o0) = v0;
            *(float2*)(out + o1) = v1;
        }
    }
}

// ---------------------------------------------------------------------------
// GroupNorm: one block per (batch, group).
// ---------------------------------------------------------------------------
__global__ __launch_bounds__(256) void groupnorm(
    const float* __restrict__ x, const float* __restrict__ w,
    const float* __restrict__ bb, float* __restrict__ h)
{
    const int bg = blockIdx.x;
    const int b  = bg >> 5;
    const int g  = bg & 31;
    const size_t off = (size_t)b * CH * SEQ + (size_t)g * CPG * SEQ;
    const float* xp = x + off;
    float* hp = h + off;
    const int n = CPG * SEQ;

    float s = 0.f, s2 = 0.f;
    for (int i = threadIdx.x * 4; i < n; i += 1024) {
        float4 v = *(const float4*)(xp + i);
        s  += v.x + v.y + v.z + v.w;
        s2 += v.x * v.x + v.y * v.y + v.z * v.z + v.w * v.w;
    }
#pragma unroll
    for (int o = 16; o; o >>= 1) {
        s  += __shfl_xor_sync(0xffffffffu, s,  o);
        s2 += __shfl_xor_sync(0xffffffffu, s2, o);
    }
    __shared__ float ws[8], ws2[8];
    const int wi = threadIdx.x >> 5, li = threadIdx.x & 31;
    if (li == 0) { ws[wi] = s; ws2[wi] = s2; }
    __syncthreads();
    if (threadIdx.x == 0) {
        float S = 0.f, S2 = 0.f;
#pragma unroll
        for (int k = 0; k < 8; k++) { S += ws[k]; S2 += ws2[k]; }
        const float mean = S / n;
        const float var  = S2 / n - mean * mean;
        ws[0]  = mean;
        ws2[0] = rsqrtf(var + 1e-5f);
    }
    __syncthreads();
    const float mean = ws[0], rstd = ws2[0];
    for (int i = threadIdx.x * 4; i < n; i += 1024) {
        const int c = g * CPG + (i >> 10);
        const float sc = rstd * w[c];
        const float sb = bb[c] - mean * sc;
        float4 v = *(const float4*)(xp + i);
        v.x = v.x * sc + sb; v.y = v.y * sc + sb;
        v.z = v.z * sc + sb; v.w = v.w * sc + sb;
        *(float4*)(hp + i) = v;
    }
}

// ---------------------------------------------------------------------------
// tf32 flash attention with register-prefetched K/V tiles.
// Block = (b,h) x 128-query tile; 8 warps x 16 rows.
// smem (floats): Qs[64][132] | Ks[64][68] | Vs[64][68] | Ps[128][68]
// ---------------------------------------------------------------------------
#define Q_ST 132
#define K_ST 68
__global__ __launch_bounds__(256, 2) void attn_tf32(
    const float* __restrict__ qkv, float* __restrict__ ao)
{
    extern __shared__ float sm[];
    float* Qs = sm;                  // 8448
    float* Ks = sm + 8448;           // 4352
    float* Vs = sm + 12800;          // 4352
    float* Ps = sm + 17152;          // 8704  (total 25856 floats)

    const int bh = blockIdx.y;
    const int b  = bh >> 4;
    const int hh = bh & 15;
    const int t0 = blockIdx.x * 128;
    const float* base = qkv + ((size_t)b * 3 * CH + (size_t)hh * 192) * SEQ;

    const int tid  = threadIdx.x;
    const int lane = tid & 31;
    const int wid  = tid >> 5;
    const int lg   = lane >> 2;
    const int lt   = lane & 3;
    const int tr0  = wid * 16;

    // Load Q tile (tf32-converted): Qs[c][t]
#pragma unroll
    for (int j = 0; j < 8; j++) {
        const int lin = tid + j * 256;
        const int c  = lin >> 5;
        const int tp = (lin & 31) * 4;
        float4 v = *(const float4*)(base + (size_t)c * SEQ + t0 + tp);
        v.x = to_tf32(v.x); v.y = to_tf32(v.y); v.z = to_tf32(v.z); v.w = to_tf32(v.w);
        *(float4*)&Qs[c * Q_ST + tp] = v;
    }

    float O[8][4];
#pragma unroll
    for (int nt = 0; nt < 8; nt++)
#pragma unroll
        for (int r = 0; r < 4; r++) O[nt][r] = 0.f;
    float m0 = -1e30f, m1 = -1e30f, l0 = 0.f, l1 = 0.f;

    // prefetch K/V tile 0 into registers
    float4 kreg[4], vreg[4];
#pragma unroll
    for (int j = 0; j < 4; j++) {
        const int lin = tid + j * 256;
        const int c  = lin >> 4;
        const int sp = (lin & 15) * 4;
        kreg[j] = *(const float4*)(base + (size_t)(64 + c)  * SEQ + sp);
        vreg[j] = *(const float4*)(base + (size_t)(128 + c) * SEQ + sp);
    }

    for (int st = 0; st < SEQ / 64; st++) {
        __syncthreads();   // previous iteration's K/V/P reads complete
        // commit prefetched tile to smem (RNA tf32, unchanged math)
#pragma unroll
        for (int j = 0; j < 4; j++) {
            const int lin = tid + j * 256;
            const int c  = lin >> 4;
            const int sp = (lin & 15) * 4;
            float4 k = kreg[j], v = vreg[j];
            k.x = to_tf32(k.x); k.y = to_tf32(k.y); k.z = to_tf32(k.z); k.w = to_tf32(k.w);
            v.x = to_tf32(v.x); v.y = to_tf32(v.y); v.z = to_tf32(v.z); v.w = to_tf32(v.w);
            *(float4*)&Ks[c * K_ST + sp] = k;
            *(float4*)&Vs[c * K_ST + sp] = v;
        }
        __syncthreads();
        // issue next tile's loads; latency hidden under compute below
        if (st + 1 < SEQ / 64) {
            const int s1 = (st + 1) * 64;
#pragma unroll
            for (int j = 0; j < 4; j++) {
                const int lin = tid + j * 256;
                const int c  = lin >> 4;
                const int sp = (lin & 15) * 4;
                kreg[j] = *(const float4*)(base + (size_t)(64 + c)  * SEQ + s1 + sp);
                vreg[j] = *(const float4*)(base + (size_t)(128 + c) * SEQ + s1 + sp);
            }
        }

        // S = Q^T K
        float S[8][4];
#pragma unroll
        for (int nt = 0; nt < 8; nt++)
#pragma unroll
            for (int r = 0; r < 4; r++) S[nt][r] = 0.f;
#pragma unroll
        for (int kk = 0; kk < 64; kk += 8) {
            float a[4];
            a[0] = Qs[(kk + lt) * Q_ST + tr0 + lg];
            a[1] = Qs[(kk + lt) * Q_ST + tr0 + 8 + lg];
            a[2] = Qs[(kk + 4 + lt) * Q_ST + tr0 + lg];
            a[3] = Qs[(kk + 4 + lt) * Q_ST + tr0 + 8 + lg];
#pragma unroll
            for (int nt = 0; nt < 8; nt++) {
                float bb[2];
                bb[0] = Ks[(kk + lt) * K_ST + nt * 8 + lg];
                bb[1] = Ks[(kk + 4 + lt) * K_ST + nt * 8 + lg];
                mma_tf32(S[nt], a, bb);
            }
        }

        // online softmax
        float mx0 = -1e30f, mx1 = -1e30f;
#pragma unroll
        for (int nt = 0; nt < 8; nt++) {
            S[nt][0] *= 0.125f; S[nt][1] *= 0.125f;
            S[nt][2] *= 0.125f; S[nt][3] *= 0.125f;
            mx0 = fmaxf(mx0, fmaxf(S[nt][0], S[nt][1]));
            mx1 = fmaxf(mx1, fmaxf(S[nt][2], S[nt][3]));
        }
#pragma unroll
        for (int o = 1; o < 4; o <<= 1) {
            mx0 = fmaxf(mx0, __shfl_xor_sync(0xffffffffu, mx0, o, 4));
            mx1 = fmaxf(mx1, __shfl_xor_sync(0xffffffffu, mx1, o, 4));
        }
        const float mn0 = fmaxf(m0, mx0);
        const float mn1 = fmaxf(m1, mx1);
        const float cr0 = __expf(m0 - mn0);
        const float cr1 = __expf(m1 - mn1);
        float sum0 = 0.f, sum1 = 0.f;
#pragma unroll
        for (int nt = 0; nt < 8; nt++) {
            S[nt][0] = __expf(S[nt][0] - mn0);
            S[nt][1] = __expf(S[nt][1] - mn0);
            S[nt][2] = __expf(S[nt][2] - mn1);
            S[nt][3] = __expf(S[nt][3] - mn1);
            sum0 += S[nt][0] + S[nt][1];
            sum1 += S[nt][2] + S[nt][3];
        }
#pragma unroll
        for (int o = 1; o < 4; o <<= 1) {
            sum0 += __shfl_xor_sync(0xffffffffu, sum0, o, 4);
            sum1 += __shfl_xor_sync(0xffffffffu, sum1, o, 4);
        }
        l0 = l0 * cr0 + sum0;
        l1 = l1 * cr1 + sum1;
        m0 = mn0; m1 = mn1;
#pragma unroll
        for (int nt = 0; nt < 8; nt++) {
            O[nt][0] *= cr0; O[nt][1] *= cr0;
            O[nt][2] *= cr1; O[nt][3] *= cr1;
        }

        // stage P (warp-private rows) as tf32
        __syncwarp();
#pragma unroll
        for (int nt = 0; nt < 8; nt++) {
            const int col = nt * 8 + 2 * lt;
            *(float2*)&Ps[(tr0 + lg) * K_ST + col] =
                make_float2(to_tf32(S[nt][0]), to_tf32(S[nt][1]));
            *(float2*)&Ps[(tr0 + 8 + lg) * K_ST + col] =
                make_float2(to_tf32(S[nt][2]), to_tf32(S[nt][3]));
        }
        __syncwarp();

        // O += P * V^T
#pragma unroll
        for (int kk = 0; kk < 64; kk += 8) {
            float a[4];
            a[0] = Ps[(tr0 + lg) * K_ST + kk + lt];
            a[1] = Ps[(tr0 + 8 + lg) * K_ST + kk + lt];
            a[2] = Ps[(tr0 + lg) * K_ST + kk + 4 + lt];
            a[3] = Ps[(tr0 + 8 + lg) * K_ST + kk + 4 + lt];
#pragma unroll
            for (int nt = 0; nt < 8; nt++) {
                float bb[2];
                bb[0] = Vs[(nt * 8 + lg) * K_ST + kk + lt];
                bb[1] = Vs[(nt * 8 + lg) * K_ST + kk + 4 + lt];
                mma_tf32(O[nt], a, bb);
            }
        }
    }

    // normalize + transpose through Qs for coalesced store
    const float inv0 = 1.f / l0;
    const float inv1 = 1.f / l1;
    __syncthreads();
#pragma unroll
    for (int nt = 0; nt < 8; nt++) {
        const int col = nt * 8 + 2 * lt;
        Qs[(col) * Q_ST + tr0 + lg]         = O[nt][0] * inv0;
        Qs[(col + 1) * Q_ST + tr0 + lg]     = O[nt][1] * inv0;
        Qs[(col) * Q_ST + tr0 + 8 + lg]     = O[nt][2] * inv1;
        Qs[(col + 1) * Q_ST + tr0 + 8 + lg] = O[nt][3] * inv1;
    }
    __syncthreads();
#pragma unroll
    for (int j = 0; j < 8; j++) {
        const int lin = tid + j * 256;
        const int c  = lin >> 5;
        const int tp = (lin & 31) * 4;
        *(float4*)(ao + ((size_t)b * CH + (size_t)hh * 64 + c) * SEQ + t0 + tp) =
            *(float4*)&Qs[c * Q_ST + tp];
    }
}

// ---------------------------------------------------------------------------
// Last layer specializations (only column t=0 of the output is consumed)
// ---------------------------------------------------------------------------
__global__ __launch_bounds__(256) void gemv_q0(
    const float* __restrict__ W, const float* __restrict__ h,
    const float* __restrict__ bias, float* __restrict__ q0)
{
    const int gw = blockIdx.x * 8 + (threadIdx.x >> 5);
    const int lane = threadIdx.x & 31;
    const int b = gw >> 10;
    const int m = gw & 1023;                       // h*64 + j
    const int row = (m >> 6) * 192 + (m & 63);     // global q row
    float s = 0.f;
    for (int k = lane; k < CH; k += 32)
        s += W[(size_t)row * CH + k] * h[((size_t)b * CH + k) * SEQ];
#pragma unroll
    for (int o = 16; o; o >>= 1) s += __shfl_xor_sync(0xffffffffu, s, o);
    if (lane == 0) q0[b * CH + m] = s + bias[row];
}

__global__ __launch_bounds__(256) void attn_last(
    const float* __restrict__ qkv, const float* __restrict__ q0,
    float* __restrict__ o0)
{
    __shared__ float q[64];
    __shared__ float lgt[SEQ];
    __shared__ float red[256];
    __shared__ float s_m, s_l;

    const int b  = blockIdx.x >> 4;
    const int hh = blockIdx.x & 15;
    const int tid = threadIdx.x;
    const float* base = qkv + ((size_t)b * 3 * CH + (size_t)hh * 192) * SEQ;

    if (tid < 64) q[tid] = q0[b * CH + hh * 64 + tid];
    __syncthreads();

#pragma unroll
    for (int j = 0; j < 4; j++) {
        const int s = tid + j * 256;
        float acc = 0.f;
#pragma unroll 8
        for (int c = 0; c < 64; c++)
            acc += q[c] * base[(size_t)(64 + c) * SEQ + s];
        lgt[s] = acc * 0.125f;
    }
    __syncthreads();

    float mx = -1e30f;
#pragma unroll
    for (int j = 0; j < 4; j++) mx = fmaxf(mx, lgt[tid + j * 256]);
    red[tid] = mx;
    __syncthreads();
    for (int stp = 128; stp; stp >>= 1) {
        if (tid < stp) red[tid] = fmaxf(red[tid], red[tid + stp]);
        __syncthreads();
    }
    if (tid == 0) s_m = red[0];
    __syncthreads();
    const float mxv = s_m;

    float sum = 0.f;
#pragma unroll
    for (int j = 0; j < 4; j++) {
        const int s = tid + j * 256;
        const float p = __expf(lgt[s] - mxv);
        lgt[s] = p;
        sum += p;
    }
    __syncthreads();
    red[tid] = sum;
    __syncthreads();
    for (int stp = 128; stp; stp >>= 1) {
        if (tid < stp) red[tid] += red[tid + stp];
        __syncthreads();
    }
    if (tid == 0) s_l = red[0];
    __syncthreads();

    const int c  = tid >> 2;
    const int si = tid & 3;
    float part = 0.f;
    const float* vrow = base + (size_t)(128 + c) * SEQ;
    for (int s = si * 256; s < si * 256 + 256; s++) part += lgt[s] * vrow[s];
    red[tid] = part;
    __syncthreads();
    if (tid < 64) {
        const float o = (red[tid * 4] + red[tid * 4 + 1] +
                         red[tid * 4 + 2] + red[tid * 4 + 3]) / s_l;
        o0[b * CH + hh * 64 + tid] = o;
    }
}

__global__ __launch_bounds__(256) void proj_last(
    const float* __restrict__ W, const float* __restrict__ o0,
    const float* __restrict__ bias, const float* __restrict__ x,
    float* __restrict__ out)
{
    const int gw = blockIdx.x * 8 + (threadIdx.x >> 5);
    const int lane = threadIdx.x & 31;
    const int b = gw >> 10;
    const int m = gw & 1023;
    float s = 0.f;
    for (int k = lane; k < CH; k += 32)
        s += W[(size_t)m * CH + k] * o0[b * CH + k];
#pragma unroll
    for (int o = 16; o; o >>= 1) s += __shfl_xor_sync(0xffffffffu, s, o);
    if (lane == 0)
        out[b * CH + m] = s + bias[m] + x[((size_t)b * CH + m) * SEQ];
}

// ---------------------------------------------------------------------------
extern "C" void kernel_launch(void* const* d_in, const int* in_sizes, int n_in,
                              void* d_out, int out_size)
{
    const float* speech = (const float*)d_in[0];
    const float* init_w = (const float*)d_in[1];
    const float* init_b = (const float*)d_in[2];
    const float* gn_w   = (const float*)d_in[3];
    const float* gn_b   = (const float*)d_in[4];
    const float* qkv_w  = (const float*)d_in[5];
    const float* qkv_b  = (const float*)d_in[6];
    const float* proj_w = (const float*)d_in[7];
    const float* proj_b = (const float*)d_in[8];
    float* out = (float*)d_out;

    float *px, *ph, *pqkv, *pao, *pq0, *po0;
    cudaGetSymbolAddress((void**)&px,   g_x);
    cudaGetSymbolAddress((void**)&ph,   g_h);
    cudaGetSymbolAddress((void**)&pqkv, g_qkv);
    cudaGetSymbolAddress((void**)&pao,  g_ao);
    cudaGetSymbolAddress((void**)&pq0,  g_q0);
    cudaGetSymbolAddress((void**)&po0,  g_o0);

    const int ATTN_SMEM = 25856 * sizeof(float);  // 103424 B
    cudaFuncSetAttribute(attn_tf32, cudaFuncAttributeMaxDynamicSharedMemorySize, ATTN_SMEM);

    // init projection: x = init_w @ speech + init_b   (M=1024, N=1024, K=80)
    gemm_tf32<<<dim3(8, 8, 8), 256>>>(init_w, speech, init_b, nullptr,
                                      px, CH, SEQ, SPECD, (size_t)CH * SEQ, 0);

    for (int l = 0; l < LAYERS - 1; l++) {
        groupnorm<<<256, 256>>>(px, gn_w + l * CH, gn_b + l * CH, ph);
        gemm_tf32<<<dim3(8, 24, 8), 256>>>(
            qkv_w + (size_t)l * 3 * CH * CH, ph, qkv_b + (size_t)l * 3 * CH,
            nullptr, pqkv, 3 * CH, SEQ, CH, (size_t)3 * CH * SEQ, 0);
        attn_tf32<<<dim3(8, 128), 256, ATTN_SMEM>>>(pqkv, pao);
        gemm_tf32<<<dim3(8, 8, 8), 256>>>(
            proj_w + (size_t)l * CH * CH, pao, proj_b + (size_t)l * CH,
            px, px, CH, SEQ, CH, (size_t)CH * SEQ, 0);
    }

    // last layer: only t=0 output needed
    {
        const int l = LAYERS - 1;
        groupnorm<<<256, 256>>>(px, gn_w + l * CH, gn_b + l * CH, ph);
        gemm_tf32<<<dim3(8, 16, 8), 256>>>(
            qkv_w + (size_t)l * 3 * CH * CH, ph,
            qkv_b + (size_t)l * 3 * CH, nullptr,
            pqkv, 2 * CH, SEQ, CH, (size_t)3 * CH * SEQ, 1);
        gemv_q0<<<1024, 256>>>(qkv_w + (size_t)l * 3 * CH * CH, ph,
                               qkv_b + (size_t)l * 3 * CH, pq0);
        attn_last<<<128, 256>>>(pqkv, pq0, po0);
        proj_last<<<1024, 256>>>(proj_w + (size_t)l * CH * CH, po0,
                                 proj_b + (size_t)l * CH, px, out);
    }
}